// round 11
// baseline (speedup 1.0000x reference)
#include <cuda_runtime.h>
#include <cuda_bf16.h>
#include <cstdint>

#define T_LEN      131072
#define N_ST       256
#define ROWS_CHUNK 32                    // rows per cost buffer
#define CBUF_BYTES 32768                 // 32 rows x 1KB
#define NCHUNK     (T_LEN / ROWS_CHUNK)  // 4096
#define UHALF      16384                 // 32 u-slots x 512B
#define SMEM_TOTAL (3 * CBUF_BYTES + 2 * UHALF + 128)
#define FLT_MIN_N  1.17549435e-38f

// cost[t][s] = -log(probs[t][s]) (+64 pad rows)
static __device__ float g_cost[(size_t)(T_LEN + 64) * N_ST];
// exported path metrics u_t[128], t = 0..T (u_0 = zeros)
static __device__ float g_u[(size_t)(T_LEN + 1) * 128];

// ---------------------------------------------------------------------------
// Phase A: parallel likelihoods (validated R6: FTZ emulation is load-bearing).
// ---------------------------------------------------------------------------
__global__ void __launch_bounds__(256) va_cost_kernel(const float* __restrict__ rx,
                                                      const float* __restrict__ h,
                                                      float* __restrict__ out) {
    __shared__ float sp[N_ST];
    __shared__ float hs[8];
    const int tid = threadIdx.x;
    if (tid < 8) hs[tid] = h[tid];
    __syncthreads();
    {
        float acc = 0.0f;
#pragma unroll
        for (int j = 0; j < 8; ++j) {
            float sym = ((tid >> (7 - j)) & 1) ? -1.0f : 1.0f;
            acc += sym * hs[j];
        }
        sp[tid] = acc;
    }
    __syncthreads();

    const int lane = tid & 31;
    const int t    = blockIdx.x * 8 + (tid >> 5);
    const float r  = rx[t];

    float p[8];
    float acc = 0.0f;
#pragma unroll
    for (int k = 0; k < 8; ++k) {
        float d = r - sp[lane + 32 * k];
        float a = (-(d * d)) / 0.2f;
        float e = expf(a);
        p[k] = (e < FLT_MIN_N) ? 0.0f : e;   // FTZ
        acc += p[k];
    }
#pragma unroll
    for (int off = 16; off > 0; off >>= 1)
        acc += __shfl_down_sync(0xffffffffu, acc, off);
    const float S = __shfl_sync(0xffffffffu, acc, 0);

    float bv = -1.0f; int bi = 0;
#pragma unroll
    for (int k = 0; k < 8; ++k) {
        float q = __fdiv_rn(p[k], S);
        q = (q < FLT_MIN_N) ? 0.0f : q;      // FTZ
        int s = lane + 32 * k;
        if (q > bv) { bv = q; bi = s; }
        g_cost[(size_t)t * N_ST + s] = -logf(q);
    }
#pragma unroll
    for (int off = 16; off > 0; off >>= 1) {
        float ov = __shfl_xor_sync(0xffffffffu, bv, off);
        int   oi = __shfl_xor_sync(0xffffffffu, bi, off);
        if (ov > bv || (ov == bv && oi < bi)) { bv = ov; bi = oi; }
    }

    if (lane == 0) {
        out[T_LEN + t]     = (float)(bi & 1);
        out[2 * T_LEN + t] = bv;
    }
}

// --- small asm helpers ------------------------------------------------------
__device__ __forceinline__ void st_rel(int* p, int v) {
    asm volatile("st.release.cta.shared.b32 [%0], %1;"
                 :: "r"((unsigned)__cvta_generic_to_shared(p)), "r"(v) : "memory");
}
__device__ __forceinline__ int ld_acq(int* p) {
    int v;
    asm volatile("ld.acquire.cta.shared.b32 %0, [%1];"
                 : "=r"(v) : "r"((unsigned)__cvta_generic_to_shared(p)) : "memory");
    return v;
}
__device__ __forceinline__ void mbar_init(unsigned a, unsigned cnt) {
    asm volatile("mbarrier.init.shared.b64 [%0], %1;" :: "r"(a), "r"(cnt) : "memory");
}
__device__ __forceinline__ void mbar_expect_tx(unsigned a, unsigned bytes) {
    asm volatile("mbarrier.arrive.expect_tx.shared.b64 _, [%0], %1;"
                 :: "r"(a), "r"(bytes) : "memory");
}
__device__ __forceinline__ void mbar_wait(unsigned a, int par) {
    asm volatile(
        "{\n\t.reg .pred P;\n"
        "W%=:\n\t"
        "mbarrier.try_wait.parity.acquire.cta.shared::cta.b64 P, [%0], %1, 0x989680;\n\t"
        "@!P bra W%=;\n\t}"
        :: "r"(a), "r"(par) : "memory");
}
__device__ __forceinline__ void bulk_g2s(unsigned sdst, const void* gsrc,
                                         unsigned bytes, unsigned mbar) {
    asm volatile("cp.async.bulk.shared::cta.global.mbarrier::complete_tx::bytes "
                 "[%0], [%1], %2, [%3];"
                 :: "r"(sdst), "l"(gsrc), "r"(bytes), "r"(mbar) : "memory");
}

// ---------------------------------------------------------------------------
// Phase B: ONE serial warp + one helper warp.
//   warp 0: recursion. Per step only: 2 LDS.128, 8 SHFL, 8 FADD, 4 FMNMX,
//           1 STS.128. Costs arrive via 1D TMA bulk (3 x 32KB buffers,
//           1 instruction + 1 mbarrier wait per 32 steps). u_{t+1} goes to a
//           2x16KB smem ring.
//   warp 1: flushes completed u halves to g_u with cp.async.bulk S->G;
//           handshake via release/acquire counters (prod/done).
// ---------------------------------------------------------------------------
__global__ void __launch_bounds__(64) va_viterbi_kernel() {
    extern __shared__ char smem[];
    char* cbuf = smem;                       // 3 x 32KB cost buffers
    char* ubuf = smem + 3 * CBUF_BYTES;      // 2 x 16KB u halves
    char* ctrl = smem + 3 * CBUF_BYTES + 2 * UHALF;
    int*  prod = (int*)(ctrl + 64);          // warp0 -> warp1: chunks produced
    int*  done = (int*)(ctrl + 96);          // warp1 -> warp0: chunks flushed
    const unsigned mb0 = (unsigned)__cvta_generic_to_shared(ctrl); // 3 mbarriers

    const int tid  = threadIdx.x;
    const int lane = tid & 31;
    const int warp = tid >> 5;

    if (tid == 0) {
        mbar_init(mb0, 1); mbar_init(mb0 + 8, 1); mbar_init(mb0 + 16, 1);
        *prod = 0; *done = -1;
    }
    __syncthreads();

    if (warp == 0) {
        // prefill 3 cost buffers
        if (lane == 0) {
#pragma unroll
            for (int b = 0; b < 3; ++b) {
                mbar_expect_tx(mb0 + b * 8, CBUF_BYTES);
                bulk_g2s((unsigned)__cvta_generic_to_shared(cbuf + b * CBUF_BYTES),
                         g_cost + (size_t)b * ROWS_CHUNK * N_ST, CBUF_BYTES, mb0 + b * 8);
            }
        }

        float u0 = 0.0f, u1 = 0.0f, u2 = 0.0f, u3 = 0.0f;
        const int src0 = (2 * lane) & 31;
        const int src1 = (2 * lane + 1) & 31;

        for (int c = 0; c < NCHUNK; ++c) {
            const int b   = c % 3;
            const int par = (c / 3) & 1;
            mbar_wait(mb0 + b * 8, par);              // cost chunk resident
            while (ld_acq(done) < c - 2) { }          // u half free

            const char* crd = cbuf + b * CBUF_BYTES + lane * 32;
            char*       uwr = ubuf + (c & 1) * UHALF + lane * 16;
#pragma unroll 1
            for (int q = 0; q < 4; ++q) {
#pragma unroll
                for (int k = 0; k < 8; ++k) {
                    float4 ca = *(const float4*)(crd + k * 1024);
                    float4 cb = *(const float4*)(crd + k * 1024 + 16);

                    float a0 = __shfl_sync(0xffffffffu, u0, src0);
                    float a1 = __shfl_sync(0xffffffffu, u1, src0);
                    float a2 = __shfl_sync(0xffffffffu, u2, src0);
                    float a3 = __shfl_sync(0xffffffffu, u3, src0);
                    float b0 = __shfl_sync(0xffffffffu, u0, src1);
                    float b1 = __shfl_sync(0xffffffffu, u1, src1);
                    float b2 = __shfl_sync(0xffffffffu, u2, src1);
                    float b3 = __shfl_sync(0xffffffffu, u3, src1);
                    u0 = fminf(a0 + ca.x, a1 + ca.y);
                    u1 = fminf(a2 + ca.z, a3 + ca.w);
                    u2 = fminf(b0 + cb.x, b1 + cb.y);
                    u3 = fminf(b2 + cb.z, b3 + cb.w);

                    *(float4*)(uwr + k * 512) = make_float4(u0, u1, u2, u3);
                }
                crd += 8 * 1024;
                uwr += 8 * 512;
            }

            __syncwarp();                    // all lanes' STS ordered before release
            if (lane == 0) {
                st_rel(prod, c + 1);         // half (c&1) ready for flush
                if (c + 3 < NCHUNK) {        // reload this buffer 3 chunks ahead
                    mbar_expect_tx(mb0 + b * 8, CBUF_BYTES);
                    bulk_g2s((unsigned)__cvta_generic_to_shared(cbuf + b * CBUF_BYTES),
                             g_cost + (size_t)(c + 3) * ROWS_CHUNK * N_ST,
                             CBUF_BYTES, mb0 + b * 8);
                }
            }
        }
    } else {
        // warp 1: u_0 = zeros, then flush halves as they complete
        *(float4*)(g_u + lane * 4) = make_float4(0.f, 0.f, 0.f, 0.f);
        if (lane == 0) {
            for (int c = 0; c < NCHUNK; ++c) {
                while (ld_acq(prod) < c + 1) { }
                asm volatile("fence.proxy.async.shared::cta;" ::: "memory");
                unsigned ssrc = (unsigned)__cvta_generic_to_shared(ubuf + (c & 1) * UHALF);
                float* gdst = g_u + (size_t)(c * ROWS_CHUNK + 1) * 128;
                asm volatile("cp.async.bulk.global.shared::cta.bulk_group [%0], [%1], %2;"
                             :: "l"(gdst), "r"(ssrc), "r"((unsigned)UHALF) : "memory");
                asm volatile("cp.async.bulk.commit_group;" ::: "memory");
                asm volatile("cp.async.bulk.wait_group 0;" ::: "memory");
                st_rel(done, c);
            }
        }
    }
}

// ---------------------------------------------------------------------------
// Phase C: parallel bits. One warp per t: bit_t = argmin(u_t) % 2,
// first-index ties (u >= +0, +inf ok -> uint order == float order).
// ---------------------------------------------------------------------------
__global__ void __launch_bounds__(256) va_bits_kernel(float* __restrict__ out) {
    const int lane = threadIdx.x & 31;
    const int t    = blockIdx.x * 8 + (threadIdx.x >> 5);
    const float4 uu = *(const float4*)(g_u + (size_t)t * 128 + lane * 4);
    const int base_li = 4 * lane;
    float lv = uu.x; int li = base_li;
    if (uu.y < lv) { lv = uu.y; li = base_li + 1; }
    if (uu.z < lv) { lv = uu.z; li = base_li + 2; }
    if (uu.w < lv) { lv = uu.w; li = base_li + 3; }
    unsigned lb = __float_as_uint(lv);
    unsigned mv, idx;
    asm volatile("redux.sync.min.u32 %0, %1, 0xffffffff;" : "=r"(mv) : "r"(lb));
    unsigned cand = (lb == mv) ? (unsigned)li : 0xffffffffu;
    asm volatile("redux.sync.min.u32 %0, %1, 0xffffffff;" : "=r"(idx) : "r"(cand));
    if (lane == 0) out[t] = (idx & 1u) ? 1.0f : 0.0f;
}

// ---------------------------------------------------------------------------
// out layout = [detected(T) | confident_bits(T) | confidence(T)], f32.
// ---------------------------------------------------------------------------
extern "C" void kernel_launch(void* const* d_in, const int* in_sizes, int n_in,
                              void* d_out, int out_size) {
    const float* rx = (const float*)d_in[0];
    const float* h  = (const float*)d_in[1];
    if (n_in >= 2 && in_sizes[0] == 8) {   // defensive: inputs swapped
        rx = (const float*)d_in[1];
        h  = (const float*)d_in[0];
    }
    float* out = (float*)d_out;
    cudaFuncSetAttribute(va_viterbi_kernel,
                         cudaFuncAttributeMaxDynamicSharedMemorySize, SMEM_TOTAL);
    va_cost_kernel<<<T_LEN / 8, 256>>>(rx, h, out);
    va_viterbi_kernel<<<1, 64, SMEM_TOTAL>>>();
    va_bits_kernel<<<T_LEN / 8, 256>>>(out);
}